// round 3
// baseline (speedup 1.0000x reference)
#include <cuda_runtime.h>
#include <math.h>

#define NN 100000
#define EE 1600000

// Scratch (allocation-free rule: __device__ globals)
__device__ __align__(16) float g_Y[NN * 32];     // [Y0(16) | Y1(16)] per node, one 128B line
__device__ __align__(16) float g_R1[NN * 16];    // x@root1 + b1
__device__ __align__(16) float g_acc1[NN * 16];  // layer-1 scatter accumulator
__device__ float g_deg[NN];                      // in-degree (shared by both layers)
__device__ __align__(16) float g_Z[NN * 20];     // [Z0(10) | Z1(10)] per node (80B row)
__device__ __align__(16) float g_R2[NN * 10];    // h@root2 + b2
__device__ __align__(16) float g_acc2[NN * 12];  // layer-2 accumulator (48B rows)

// ---------------------------------------------------------------------------
// Node kernel 1: Y0 = x@W1[0], Y1 = x@W1[1], R1 = x@root1 + b1; zero acc1/deg
// ---------------------------------------------------------------------------
__global__ void node1_kernel(const float* __restrict__ x,
                             const float* __restrict__ W1,
                             const float* __restrict__ root1,
                             const float* __restrict__ b1)
{
    __shared__ float sW[1024];   // W1[k][i][o] : k*512 + i*16 + o
    __shared__ float sR[512];    // root1[i][o] : i*16 + o
    __shared__ float sB[16];
    for (int t = threadIdx.x; t < 1024; t += blockDim.x) sW[t] = W1[t];
    for (int t = threadIdx.x; t < 512;  t += blockDim.x) sR[t] = root1[t];
    if (threadIdx.x < 16) sB[threadIdx.x] = b1[threadIdx.x];
    __syncthreads();

    int n = blockIdx.x * blockDim.x + threadIdx.x;
    if (n >= NN) return;

    float xv[32];
    const float4* xp = (const float4*)(x + (size_t)n * 32);
    #pragma unroll
    for (int i = 0; i < 8; i++) {
        float4 t = xp[i];
        xv[4*i+0] = t.x; xv[4*i+1] = t.y; xv[4*i+2] = t.z; xv[4*i+3] = t.w;
    }

    float* Yp = g_Y  + (size_t)n * 32;
    float* Rp = g_R1 + (size_t)n * 16;
    for (int o = 0; o < 16; o++) {
        float y0 = 0.f, y1 = 0.f, r = sB[o];
        #pragma unroll
        for (int i = 0; i < 32; i++) {
            y0 = fmaf(xv[i], sW[i * 16 + o], y0);
            y1 = fmaf(xv[i], sW[512 + i * 16 + o], y1);
            r  = fmaf(xv[i], sR[i * 16 + o], r);
        }
        Yp[o] = y0; Yp[16 + o] = y1; Rp[o] = r;
    }

    float4 zero = make_float4(0.f, 0.f, 0.f, 0.f);
    float4* ap = (float4*)(g_acc1 + (size_t)n * 16);
    ap[0] = zero; ap[1] = zero; ap[2] = zero; ap[3] = zero;
    g_deg[n] = 0.f;
}

// ---------------------------------------------------------------------------
// Edge kernel 1: gather Y[src], lerp by basis, atomicAdd into acc1[dst]
// NOTE: edge_index is int32 (jax without x64 silently downcasts int64).
// ---------------------------------------------------------------------------
__global__ void edge1_kernel(const int* __restrict__ ei,
                             const float* __restrict__ attr)
{
    int e = blockIdx.x * blockDim.x + threadIdx.x;
    if (e >= EE) return;
    int s = ei[e];
    int d = ei[EE + e];
    if ((unsigned)s >= NN || (unsigned)d >= NN) return;  // defensive
    float v  = attr[e];                         // v = edge_attr * (K-1), K=2
    float c0 = fmaxf(0.f, 1.f - fabsf(v));
    float c1 = fmaxf(0.f, 1.f - fabsf(v - 1.f));

    const float4* yp = (const float4*)(g_Y + (size_t)s * 32);
    float m[16];
    #pragma unroll
    for (int q = 0; q < 4; q++) {
        float4 a = yp[q];      // Y0 part
        float4 b = yp[q + 4];  // Y1 part
        m[4*q+0] = c0*a.x + c1*b.x;
        m[4*q+1] = c0*a.y + c1*b.y;
        m[4*q+2] = c0*a.z + c1*b.z;
        m[4*q+3] = c0*a.w + c1*b.w;
    }

    float* ap = g_acc1 + (size_t)d * 16;
    #pragma unroll
    for (int j = 0; j < 16; j++) atomicAdd(ap + j, m[j]);
    atomicAdd(&g_deg[d], 1.0f);
}

// ---------------------------------------------------------------------------
// Node kernel 2: h = elu(acc1/deg + R1); Z0=h@W2[0], Z1=h@W2[1], R2=h@root2+b2
// ---------------------------------------------------------------------------
__global__ void node2_kernel(const float* __restrict__ W2,
                             const float* __restrict__ root2,
                             const float* __restrict__ b2)
{
    __shared__ float sW[320];   // W2[k][i][o] : k*160 + i*10 + o
    __shared__ float sR[160];   // root2[i][o] : i*10 + o
    __shared__ float sB[10];
    for (int t = threadIdx.x; t < 320; t += blockDim.x) sW[t] = W2[t];
    for (int t = threadIdx.x; t < 160; t += blockDim.x) sR[t] = root2[t];
    if (threadIdx.x < 10) sB[threadIdx.x] = b2[threadIdx.x];
    __syncthreads();

    int n = blockIdx.x * blockDim.x + threadIdx.x;
    if (n >= NN) return;

    float inv = 1.f / fmaxf(g_deg[n], 1.f);
    const float* ac = g_acc1 + (size_t)n * 16;
    const float* r1 = g_R1  + (size_t)n * 16;
    float h[16];
    #pragma unroll
    for (int o = 0; o < 16; o++) {
        float t = ac[o] * inv + r1[o];
        h[o] = (t > 0.f) ? t : expm1f(t);       // ELU (alpha=1)
    }

    float* zp = g_Z  + (size_t)n * 20;
    float* r2 = g_R2 + (size_t)n * 10;
    for (int o = 0; o < 10; o++) {
        float z0 = 0.f, z1 = 0.f, r = sB[o];
        #pragma unroll
        for (int i = 0; i < 16; i++) {
            z0 = fmaf(h[i], sW[i * 10 + o], z0);
            z1 = fmaf(h[i], sW[160 + i * 10 + o], z1);
            r  = fmaf(h[i], sR[i * 10 + o], r);
        }
        zp[o] = z0; zp[10 + o] = z1; r2[o] = r;
    }

    float4 zero = make_float4(0.f, 0.f, 0.f, 0.f);
    float4* ap = (float4*)(g_acc2 + (size_t)n * 12);
    ap[0] = zero; ap[1] = zero; ap[2] = zero;
}

// ---------------------------------------------------------------------------
// Edge kernel 2: gather Z[src], lerp, atomicAdd into acc2[dst]
// ---------------------------------------------------------------------------
__global__ void edge2_kernel(const int* __restrict__ ei,
                             const float* __restrict__ attr)
{
    int e = blockIdx.x * blockDim.x + threadIdx.x;
    if (e >= EE) return;
    int s = ei[e];
    int d = ei[EE + e];
    if ((unsigned)s >= NN || (unsigned)d >= NN) return;  // defensive
    float v  = attr[e];
    float c0 = fmaxf(0.f, 1.f - fabsf(v));
    float c1 = fmaxf(0.f, 1.f - fabsf(v - 1.f));

    const float4* zp = (const float4*)(g_Z + (size_t)s * 20);
    float f[20];
    #pragma unroll
    for (int i = 0; i < 5; i++) {
        float4 t = zp[i];
        f[4*i+0] = t.x; f[4*i+1] = t.y; f[4*i+2] = t.z; f[4*i+3] = t.w;
    }

    float* ap = g_acc2 + (size_t)d * 12;
    #pragma unroll
    for (int j = 0; j < 10; j++) atomicAdd(ap + j, c0 * f[j] + c1 * f[10 + j]);
}

// ---------------------------------------------------------------------------
// Output kernel: log_softmax(acc2/deg + R2)
// ---------------------------------------------------------------------------
__global__ void out_kernel(float* __restrict__ out)
{
    int n = blockIdx.x * blockDim.x + threadIdx.x;
    if (n >= NN) return;

    float inv = 1.f / fmaxf(g_deg[n], 1.f);
    const float* ac = g_acc2 + (size_t)n * 12;
    const float* r2 = g_R2  + (size_t)n * 10;
    float o[10];
    #pragma unroll
    for (int j = 0; j < 10; j++) o[j] = ac[j] * inv + r2[j];

    float mx = o[0];
    #pragma unroll
    for (int j = 1; j < 10; j++) mx = fmaxf(mx, o[j]);
    float sum = 0.f;
    #pragma unroll
    for (int j = 0; j < 10; j++) sum += expf(o[j] - mx);
    float lse = mx + logf(sum);

    float* op = out + (size_t)n * 10;
    #pragma unroll
    for (int j = 0; j < 10; j++) op[j] = o[j] - lse;
}

// ---------------------------------------------------------------------------
extern "C" void kernel_launch(void* const* d_in, const int* in_sizes, int n_in,
                              void* d_out, int out_size)
{
    (void)out_size;
    // Resolve input order robustly from element counts.
    // Expected sizes: x=3200000 (f32), edge_index=3200000 (i32),
    // edge_attr=1600000, W1=1024, root1=512, b1=16, W2=320, root2=160, b2=10.
    int ix = -1, iei = -1, iattr = -1, iW1 = -1, ir1 = -1, ib1 = -1,
        iW2 = -1, ir2 = -1, ib2 = -1;
    int big[2]; int nbig = 0;
    for (int i = 0; i < n_in; i++) {
        switch (in_sizes[i]) {
            case 3200000: if (nbig < 2) big[nbig++] = i; break;
            case 1600000: iattr = i; break;
            case 1024:    iW1 = i; break;
            case 512:     ir1 = i; break;
            case 16:      ib1 = i; break;
            case 320:     iW2 = i; break;
            case 160:     ir2 = i; break;
            case 10:      ib2 = i; break;
            default: break;
        }
    }
    // Disambiguate {x, edge_index}: insertion order puts x before edge_index
    // (x, edge_index, edge_attr, ...); any reordering that sorts by name puts
    // edge_* first.
    if (nbig == 2) {
        bool insertion = (big[0] == 0 && big[1] == 1 && iattr == 2);
        if (insertion) { ix = big[0]; iei = big[1]; }
        else           { iei = big[0]; ix = big[1]; }
    }

    const float* x     = (const float*)d_in[ix];
    const int*   ei    = (const int*)d_in[iei];      // int32 edge_index
    const float* attr  = (const float*)d_in[iattr];
    const float* W1    = (const float*)d_in[iW1];
    const float* root1 = (const float*)d_in[ir1];
    const float* b1    = (const float*)d_in[ib1];
    const float* W2    = (const float*)d_in[iW2];
    const float* root2 = (const float*)d_in[ir2];
    const float* b2    = (const float*)d_in[ib2];
    float* out = (float*)d_out;

    node1_kernel<<<(NN + 255) / 256, 256>>>(x, W1, root1, b1);
    edge1_kernel<<<(EE + 255) / 256, 256>>>(ei, attr);
    node2_kernel<<<(NN + 255) / 256, 256>>>(W2, root2, b2);
    edge2_kernel<<<(EE + 255) / 256, 256>>>(ei, attr);
    out_kernel<<<(NN + 255) / 256, 256>>>(out);
}

// round 4
// speedup vs baseline: 1.6645x; 1.6645x over previous
#include <cuda_runtime.h>
#include <math.h>

#define NN 100000
#define EE 1600000

// Scratch (allocation-free rule: __device__ globals)
__device__ __align__(16) float g_Y[NN * 32];     // [Y0(16) | Y1(16)] per node, one 128B line
__device__ __align__(16) float g_R1[NN * 16];    // x@root1 + b1
__device__ __align__(16) float g_acc1[NN * 16];  // layer-1 scatter accumulator
__device__ float g_deg[NN];                      // in-degree (shared by both layers)
__device__ __align__(16) float g_Z[NN * 20];     // [Z0(10) | Z1(10)] per node (80B row)
__device__ __align__(16) float g_R2[NN * 10];    // h@root2 + b2
__device__ __align__(16) float g_acc2[NN * 12];  // layer-2 accumulator (48B rows)

__device__ __forceinline__ void red_add_v4(float* a, float x, float y, float z, float w) {
    asm volatile("red.global.add.v4.f32 [%0], {%1, %2, %3, %4};"
                 :: "l"(a), "f"(x), "f"(y), "f"(z), "f"(w) : "memory");
}
__device__ __forceinline__ void red_add_v2(float* a, float x, float y) {
    asm volatile("red.global.add.v2.f32 [%0], {%1, %2};"
                 :: "l"(a), "f"(x), "f"(y) : "memory");
}

// ---------------------------------------------------------------------------
// Node kernel 1: Y0 = x@W1[0], Y1 = x@W1[1], R1 = x@root1 + b1; zero acc1/deg
// ---------------------------------------------------------------------------
__global__ void node1_kernel(const float* __restrict__ x,
                             const float* __restrict__ W1,
                             const float* __restrict__ root1,
                             const float* __restrict__ b1)
{
    __shared__ float sW[1024];   // W1[k][i][o] : k*512 + i*16 + o
    __shared__ float sR[512];    // root1[i][o] : i*16 + o
    __shared__ float sB[16];
    for (int t = threadIdx.x; t < 1024; t += blockDim.x) sW[t] = W1[t];
    for (int t = threadIdx.x; t < 512;  t += blockDim.x) sR[t] = root1[t];
    if (threadIdx.x < 16) sB[threadIdx.x] = b1[threadIdx.x];
    __syncthreads();

    int n = blockIdx.x * blockDim.x + threadIdx.x;
    if (n >= NN) return;

    float xv[32];
    const float4* xp = (const float4*)(x + (size_t)n * 32);
    #pragma unroll
    for (int i = 0; i < 8; i++) {
        float4 t = xp[i];
        xv[4*i+0] = t.x; xv[4*i+1] = t.y; xv[4*i+2] = t.z; xv[4*i+3] = t.w;
    }

    float* Yp = g_Y  + (size_t)n * 32;
    float* Rp = g_R1 + (size_t)n * 16;
    for (int o = 0; o < 16; o++) {
        float y0 = 0.f, y1 = 0.f, r = sB[o];
        #pragma unroll
        for (int i = 0; i < 32; i++) {
            y0 = fmaf(xv[i], sW[i * 16 + o], y0);
            y1 = fmaf(xv[i], sW[512 + i * 16 + o], y1);
            r  = fmaf(xv[i], sR[i * 16 + o], r);
        }
        Yp[o] = y0; Yp[16 + o] = y1; Rp[o] = r;
    }

    float4 zero = make_float4(0.f, 0.f, 0.f, 0.f);
    float4* ap = (float4*)(g_acc1 + (size_t)n * 16);
    ap[0] = zero; ap[1] = zero; ap[2] = zero; ap[3] = zero;
    g_deg[n] = 0.f;
}

// ---------------------------------------------------------------------------
// Edge kernel 1: gather Y[src], lerp by basis, vector-red into acc1[dst]
// edge_index is int32 (jax without x64 silently downcasts int64).
// ---------------------------------------------------------------------------
__global__ void edge1_kernel(const int* __restrict__ ei,
                             const float* __restrict__ attr)
{
    int e = blockIdx.x * blockDim.x + threadIdx.x;
    if (e >= EE) return;
    int s = ei[e];
    int d = ei[EE + e];
    if ((unsigned)s >= NN || (unsigned)d >= NN) return;  // defensive
    float v  = attr[e];                         // v = edge_attr * (K-1), K=2
    float c0 = fmaxf(0.f, 1.f - fabsf(v));
    float c1 = fmaxf(0.f, 1.f - fabsf(v - 1.f));

    const float4* yp = (const float4*)(g_Y + (size_t)s * 32);
    float4 a0 = yp[0], a1 = yp[1], a2 = yp[2], a3 = yp[3];  // Y0
    float4 b0 = yp[4], b1 = yp[5], b2 = yp[6], b3 = yp[7];  // Y1

    float* ap = g_acc1 + (size_t)d * 16;
    red_add_v4(ap + 0,  c0*a0.x + c1*b0.x, c0*a0.y + c1*b0.y,
                        c0*a0.z + c1*b0.z, c0*a0.w + c1*b0.w);
    red_add_v4(ap + 4,  c0*a1.x + c1*b1.x, c0*a1.y + c1*b1.y,
                        c0*a1.z + c1*b1.z, c0*a1.w + c1*b1.w);
    red_add_v4(ap + 8,  c0*a2.x + c1*b2.x, c0*a2.y + c1*b2.y,
                        c0*a2.z + c1*b2.z, c0*a2.w + c1*b2.w);
    red_add_v4(ap + 12, c0*a3.x + c1*b3.x, c0*a3.y + c1*b3.y,
                        c0*a3.z + c1*b3.z, c0*a3.w + c1*b3.w);
    atomicAdd(&g_deg[d], 1.0f);
}

// ---------------------------------------------------------------------------
// Node kernel 2: h = elu(acc1/deg + R1); Z0=h@W2[0], Z1=h@W2[1], R2=h@root2+b2
// ---------------------------------------------------------------------------
__global__ void node2_kernel(const float* __restrict__ W2,
                             const float* __restrict__ root2,
                             const float* __restrict__ b2)
{
    __shared__ float sW[320];   // W2[k][i][o] : k*160 + i*10 + o
    __shared__ float sR[160];   // root2[i][o] : i*10 + o
    __shared__ float sB[10];
    for (int t = threadIdx.x; t < 320; t += blockDim.x) sW[t] = W2[t];
    for (int t = threadIdx.x; t < 160; t += blockDim.x) sR[t] = root2[t];
    if (threadIdx.x < 10) sB[threadIdx.x] = b2[threadIdx.x];
    __syncthreads();

    int n = blockIdx.x * blockDim.x + threadIdx.x;
    if (n >= NN) return;

    float inv = 1.f / fmaxf(g_deg[n], 1.f);
    const float* ac = g_acc1 + (size_t)n * 16;
    const float* r1 = g_R1  + (size_t)n * 16;
    float h[16];
    #pragma unroll
    for (int o = 0; o < 16; o++) {
        float t = ac[o] * inv + r1[o];
        h[o] = (t > 0.f) ? t : expm1f(t);       // ELU (alpha=1)
    }

    float* zp = g_Z  + (size_t)n * 20;
    float* r2 = g_R2 + (size_t)n * 10;
    for (int o = 0; o < 10; o++) {
        float z0 = 0.f, z1 = 0.f, r = sB[o];
        #pragma unroll
        for (int i = 0; i < 16; i++) {
            z0 = fmaf(h[i], sW[i * 10 + o], z0);
            z1 = fmaf(h[i], sW[160 + i * 10 + o], z1);
            r  = fmaf(h[i], sR[i * 10 + o], r);
        }
        zp[o] = z0; zp[10 + o] = z1; r2[o] = r;
    }

    float4 zero = make_float4(0.f, 0.f, 0.f, 0.f);
    float4* ap = (float4*)(g_acc2 + (size_t)n * 12);
    ap[0] = zero; ap[1] = zero; ap[2] = zero;
}

// ---------------------------------------------------------------------------
// Edge kernel 2: gather Z[src], lerp, vector-red into acc2[dst]
// ---------------------------------------------------------------------------
__global__ void edge2_kernel(const int* __restrict__ ei,
                             const float* __restrict__ attr)
{
    int e = blockIdx.x * blockDim.x + threadIdx.x;
    if (e >= EE) return;
    int s = ei[e];
    int d = ei[EE + e];
    if ((unsigned)s >= NN || (unsigned)d >= NN) return;  // defensive
    float v  = attr[e];
    float c0 = fmaxf(0.f, 1.f - fabsf(v));
    float c1 = fmaxf(0.f, 1.f - fabsf(v - 1.f));

    const float4* zp = (const float4*)(g_Z + (size_t)s * 20);
    float f[20];
    #pragma unroll
    for (int i = 0; i < 5; i++) {
        float4 t = zp[i];
        f[4*i+0] = t.x; f[4*i+1] = t.y; f[4*i+2] = t.z; f[4*i+3] = t.w;
    }
    float m[10];
    #pragma unroll
    for (int j = 0; j < 10; j++) m[j] = c0 * f[j] + c1 * f[10 + j];

    float* ap = g_acc2 + (size_t)d * 12;
    red_add_v4(ap + 0, m[0], m[1], m[2], m[3]);
    red_add_v4(ap + 4, m[4], m[5], m[6], m[7]);
    red_add_v2(ap + 8, m[8], m[9]);
}

// ---------------------------------------------------------------------------
// Output kernel: log_softmax(acc2/deg + R2)
// ---------------------------------------------------------------------------
__global__ void out_kernel(float* __restrict__ out)
{
    int n = blockIdx.x * blockDim.x + threadIdx.x;
    if (n >= NN) return;

    float inv = 1.f / fmaxf(g_deg[n], 1.f);
    const float* ac = g_acc2 + (size_t)n * 12;
    const float* r2 = g_R2  + (size_t)n * 10;
    float o[10];
    #pragma unroll
    for (int j = 0; j < 10; j++) o[j] = ac[j] * inv + r2[j];

    float mx = o[0];
    #pragma unroll
    for (int j = 1; j < 10; j++) mx = fmaxf(mx, o[j]);
    float sum = 0.f;
    #pragma unroll
    for (int j = 0; j < 10; j++) sum += expf(o[j] - mx);
    float lse = mx + logf(sum);

    float* op = out + (size_t)n * 10;
    #pragma unroll
    for (int j = 0; j < 10; j++) op[j] = o[j] - lse;
}

// ---------------------------------------------------------------------------
extern "C" void kernel_launch(void* const* d_in, const int* in_sizes, int n_in,
                              void* d_out, int out_size)
{
    (void)out_size;
    // Resolve input order robustly from element counts.
    int ix = -1, iei = -1, iattr = -1, iW1 = -1, ir1 = -1, ib1 = -1,
        iW2 = -1, ir2 = -1, ib2 = -1;
    int big[2]; int nbig = 0;
    for (int i = 0; i < n_in; i++) {
        switch (in_sizes[i]) {
            case 3200000: if (nbig < 2) big[nbig++] = i; break;
            case 1600000: iattr = i; break;
            case 1024:    iW1 = i; break;
            case 512:     ir1 = i; break;
            case 16:      ib1 = i; break;
            case 320:     iW2 = i; break;
            case 160:     ir2 = i; break;
            case 10:      ib2 = i; break;
            default: break;
        }
    }
    if (nbig == 2) {
        bool insertion = (big[0] == 0 && big[1] == 1 && iattr == 2);
        if (insertion) { ix = big[0]; iei = big[1]; }
        else           { iei = big[0]; ix = big[1]; }
    }

    const float* x     = (const float*)d_in[ix];
    const int*   ei    = (const int*)d_in[iei];      // int32 edge_index
    const float* attr  = (const float*)d_in[iattr];
    const float* W1    = (const float*)d_in[iW1];
    const float* root1 = (const float*)d_in[ir1];
    const float* b1    = (const float*)d_in[ib1];
    const float* W2    = (const float*)d_in[iW2];
    const float* root2 = (const float*)d_in[ir2];
    const float* b2    = (const float*)d_in[ib2];
    float* out = (float*)d_out;

    node1_kernel<<<(NN + 255) / 256, 256>>>(x, W1, root1, b1);
    edge1_kernel<<<(EE + 255) / 256, 256>>>(ei, attr);
    node2_kernel<<<(NN + 255) / 256, 256>>>(W2, root2, b2);
    edge2_kernel<<<(EE + 255) / 256, 256>>>(ei, attr);
    out_kernel<<<(NN + 255) / 256, 256>>>(out);
}